// round 1
// baseline (speedup 1.0000x reference)
#include <cuda_runtime.h>
#include <cuda_bf16.h>
#include <math.h>

#define Bsz   512
#define IN_   512
#define Hdim  1024
#define HEADS 16
#define DK    64
#define Wwin  32
#define Pdim  64
#define H4    4096
#define KQ    1536      // IN + H
#define EPSF  1e-5f

// ---------------- device scratch (static: no allocations allowed) ----------
__device__ float g_xh  [Bsz * KQ];          // [B, IN+H]
__device__ float g_q   [Bsz * Hdim];        // elu(xh @ Wq.T + bq)
__device__ float g_Q   [Bsz * Hdim];        // q @ Wq_a.T + bq_a
__device__ float g_pek [Wwin * Hdim];       // pe @ Wk_a[:,H:].T + bk_a  (per w)
__device__ float g_pev [Wwin * Hdim];
__device__ float g_K   [(size_t)Wwin * Bsz * Hdim];   // [W,B,H]
__device__ float g_V   [(size_t)Wwin * Bsz * Hdim];   // [W,B,H]
__device__ float g_ctx [Bsz * Hdim];
__device__ float g_attn[Bsz * Hdim];
__device__ float g_pre [Bsz * H4];

// ---------------- epilogue descriptor --------------------------------------
struct Epi {
    const float* bias;    // per-col, nullable
    const float* bias2;   // per-col, nullable
    const float* pe;      // per (row>>9, col), nullable (K/V gemm)
    int          act;     // 1 => elu
    const float* bn_g;    // nullable => no BN
    const float* bn_b;
    const float* bn_m;
    const float* bn_v;
    int          accumulate; // 1 => C += acc
};

__device__ __forceinline__ float eluf(float x) {
    return x > 0.f ? x : expm1f(x);
}

// ---------------- tiled SGEMM: C[M,N] = A[M,K] * B[N,K]^T ------------------
#define BM 128
#define BN 128
#define BK 8
#define TM 8
#define TN 8

__global__ __launch_bounds__(256, 2)
void sgemm_nt(const float* __restrict__ A, const float* __restrict__ Bw,
              float* __restrict__ C,
              int M, int N, int K, int lda, int ldb, int ldc, Epi e)
{
    __shared__ float As[BK][BM];
    __shared__ float Bs[BK][BN];

    const int tid = threadIdx.x;
    const int bm  = blockIdx.y * BM;
    const int bn  = blockIdx.x * BN;

    const int tx = tid & 15;   // 16 threads along N
    const int ty = tid >> 4;   // 16 threads along M

    const int lrow  = tid >> 1;         // 0..127
    const int lcol4 = (tid & 1) << 2;   // 0 or 4

    const float* Aptr = A + (size_t)(bm + lrow) * lda + lcol4;
    const float* Bptr = Bw + (size_t)(bn + lrow) * ldb + lcol4;

    float acc[TM][TN];
    #pragma unroll
    for (int i = 0; i < TM; i++)
        #pragma unroll
        for (int j = 0; j < TN; j++) acc[i][j] = 0.f;

    for (int k0 = 0; k0 < K; k0 += BK) {
        float4 av = *(const float4*)(Aptr + k0);
        float4 bv = *(const float4*)(Bptr + k0);
        __syncthreads();
        As[lcol4 + 0][lrow] = av.x;
        As[lcol4 + 1][lrow] = av.y;
        As[lcol4 + 2][lrow] = av.z;
        As[lcol4 + 3][lrow] = av.w;
        Bs[lcol4 + 0][lrow] = bv.x;
        Bs[lcol4 + 1][lrow] = bv.y;
        Bs[lcol4 + 2][lrow] = bv.z;
        Bs[lcol4 + 3][lrow] = bv.w;
        __syncthreads();

        #pragma unroll
        for (int k = 0; k < BK; k++) {
            float4 a0 = *(const float4*)&As[k][ty * TM];
            float4 a1 = *(const float4*)&As[k][ty * TM + 4];
            float4 b0 = *(const float4*)&Bs[k][tx * TN];
            float4 b1 = *(const float4*)&Bs[k][tx * TN + 4];
            float a[8] = {a0.x, a0.y, a0.z, a0.w, a1.x, a1.y, a1.z, a1.w};
            float b[8] = {b0.x, b0.y, b0.z, b0.w, b1.x, b1.y, b1.z, b1.w};
            #pragma unroll
            for (int i = 0; i < TM; i++)
                #pragma unroll
                for (int j = 0; j < TN; j++)
                    acc[i][j] = fmaf(a[i], b[j], acc[i][j]);
        }
    }

    #pragma unroll
    for (int i = 0; i < TM; i++) {
        int r = bm + ty * TM + i;
        #pragma unroll
        for (int j = 0; j < TN; j++) {
            int c = bn + tx * TN + j;
            float v = acc[i][j];
            if (e.bias)  v += e.bias[c];
            if (e.bias2) v += e.bias2[c];
            if (e.pe)    v += e.pe[(size_t)(r >> 9) * N + c];
            if (e.act)   v = eluf(v);
            if (e.bn_g)  v = (v - e.bn_m[c]) * e.bn_g[c] * rsqrtf(e.bn_v[c] + EPSF) + e.bn_b[c];
            float* cp = C + (size_t)r * ldc + c;
            if (e.accumulate) v += *cp;
            *cp = v;
        }
    }
}

// ---------------- small kernels --------------------------------------------
__global__ void concat_xh_kernel(const float* __restrict__ x,
                                 const float* __restrict__ ph)
{
    int idx = blockIdx.x * blockDim.x + threadIdx.x;   // B*KQ
    int r = idx / KQ, c = idx - r * KQ;
    g_xh[idx] = (c < IN_) ? x[(size_t)r * IN_ + c] : ph[(size_t)r * Hdim + (c - IN_)];
}

__global__ void pe_proj_kernel(const float* __restrict__ Wk, const float* __restrict__ bk,
                               const float* __restrict__ Wv, const float* __restrict__ bv)
{
    int w = blockIdx.x;                                  // 0..31
    int h = blockIdx.y * blockDim.x + threadIdx.x;       // 0..1023
    const float* wkr = Wk + (size_t)h * (Hdim + Pdim) + Hdim;
    const float* wvr = Wv + (size_t)h * (Hdim + Pdim) + Hdim;
    float ak = bk[h], av = bv[h];
    const float c0 = logf(10000.0f) / (float)Pdim;
    #pragma unroll
    for (int i = 0; i < Pdim / 2; i++) {
        float div = expf(-(2.0f * i) * c0);
        float ang = (float)w * div;
        float s = sinf(ang), cc = cosf(ang);
        ak += s * wkr[2 * i] + cc * wkr[2 * i + 1];
        av += s * wvr[2 * i] + cc * wvr[2 * i + 1];
    }
    g_pek[w * Hdim + h] = ak;
    g_pev[w * Hdim + h] = av;
}

// one block per batch row; 1024 threads
__global__ __launch_bounds__(1024)
void attention_kernel()
{
    int b   = blockIdx.x;
    int tid = threadIdx.x;
    int warp = tid >> 5, lane = tid & 31;

    __shared__ float qs[Hdim];
    __shared__ float S [HEADS][Wwin];
    __shared__ float ps[HEADS][Wwin];

    qs[tid] = g_Q[(size_t)b * Hdim + tid];
    __syncthreads();

    // warp w computes all 16 head scores for its window position
    {
        const float* Krow = g_K + ((size_t)warp * Bsz + b) * Hdim;
        float acc[HEADS];
        #pragma unroll
        for (int h = 0; h < HEADS; h++) acc[h] = 0.f;
        #pragma unroll
        for (int j = 0; j < 32; j++) {
            int d = lane + 32 * j;
            acc[j >> 1] = fmaf(Krow[d], qs[d], acc[j >> 1]);
        }
        #pragma unroll
        for (int h = 0; h < HEADS; h++) {
            float v = acc[h];
            #pragma unroll
            for (int off = 16; off; off >>= 1)
                v += __shfl_down_sync(0xffffffffu, v, off);
            if (lane == 0) S[h][warp] = v * 0.125f;   // 1/sqrt(64)
        }
    }
    __syncthreads();

    // softmax: warp h handles head h over 32 positions
    if (warp < HEADS) {
        float s = S[warp][lane];
        float m = s;
        #pragma unroll
        for (int off = 16; off; off >>= 1)
            m = fmaxf(m, __shfl_xor_sync(0xffffffffu, m, off));
        float ev = expf(s - m);
        float sum = ev;
        #pragma unroll
        for (int off = 16; off; off >>= 1)
            sum += __shfl_xor_sync(0xffffffffu, sum, off);
        ps[warp][lane] = ev / sum;
    }
    __syncthreads();

    // ctx[b, tid] = sum_w p[h][w] * V[w, b, tid]
    int h = tid >> 6;
    const float* Vb = g_V + (size_t)b * Hdim + tid;
    float acc = 0.f;
    #pragma unroll
    for (int w = 0; w < Wwin; w++)
        acc = fmaf(ps[h][w], Vb[(size_t)w * Bsz * Hdim], acc);
    g_ctx[(size_t)b * Hdim + tid] = acc;
}

__global__ void final_kernel(const float* __restrict__ pcell,
                             const float* __restrict__ gmm, const float* __restrict__ bb,
                             const float* __restrict__ mm, const float* __restrict__ vv,
                             float* __restrict__ out)
{
    int idx = blockIdx.x * blockDim.x + threadIdx.x;   // B*H
    int r = idx >> 10, c = idx & 1023;
    const float* p = g_pre + (size_t)r * H4;
    float iv = tanhf(p[c]);
    float f  = 1.f / (1.f + expf(-p[1024 + c]));
    float ig = 1.f / (1.f + expf(-p[2048 + c]));
    float o  = 1.f / (1.f + expf(-p[3072 + c]));
    float cell = iv * ig + pcell[idx] * f;
    float e = eluf(cell);
    out[idx] = (o * e - mm[c]) * gmm[c] * rsqrtf(vv[c] + EPSF) + bb[c];
}

// ---------------- host ------------------------------------------------------
static void launch_sgemm(const float* A, const float* Bw, float* C,
                         int M, int N, int K, int lda, int ldb, int ldc, Epi e)
{
    dim3 grid(N / BN, M / BM);
    sgemm_nt<<<grid, 256>>>(A, Bw, C, M, N, K, lda, ldb, ldc, e);
}

extern "C" void kernel_launch(void* const* d_in, const int* in_sizes, int n_in,
                              void* d_out, int out_size)
{
    const float* x      = (const float*)d_in[0];
    const float* ph     = (const float*)d_in[1];
    const float* pc     = (const float*)d_in[2];
    const float* pcells = (const float*)d_in[3];
    const float* W_ih   = (const float*)d_in[4];
    const float* b_ih   = (const float*)d_in[5];
    const float* W_hh   = (const float*)d_in[6];
    const float* W_q    = (const float*)d_in[7];
    const float* b_q    = (const float*)d_in[8];
    const float* W_ac   = (const float*)d_in[9];
    const float* b_ac   = (const float*)d_in[10];
    const float* Wq_a   = (const float*)d_in[11];
    const float* bq_a   = (const float*)d_in[12];
    const float* Wk_a   = (const float*)d_in[13];
    const float* bk_a   = (const float*)d_in[14];
    const float* Wv_a   = (const float*)d_in[15];
    const float* bv_a   = (const float*)d_in[16];
    const float* Wo_a   = (const float*)d_in[17];
    const float* bo_a   = (const float*)d_in[18];
    const float* bnag   = (const float*)d_in[19];
    const float* bnab   = (const float*)d_in[20];
    const float* bnam   = (const float*)d_in[21];
    const float* bnav   = (const float*)d_in[22];
    const float* bnpg   = (const float*)d_in[23];
    const float* bnpb   = (const float*)d_in[24];
    const float* bnpm   = (const float*)d_in[25];
    const float* bnpv   = (const float*)d_in[26];
    float* out = (float*)d_out;

    float *pxh, *pq, *pQ, *ppek, *ppev, *pK, *pV, *pctx, *pattn, *ppre;
    cudaGetSymbolAddress((void**)&pxh,  g_xh);
    cudaGetSymbolAddress((void**)&pq,   g_q);
    cudaGetSymbolAddress((void**)&pQ,   g_Q);
    cudaGetSymbolAddress((void**)&ppek, g_pek);
    cudaGetSymbolAddress((void**)&ppev, g_pev);
    cudaGetSymbolAddress((void**)&pK,   g_K);
    cudaGetSymbolAddress((void**)&pV,   g_V);
    cudaGetSymbolAddress((void**)&pctx, g_ctx);
    cudaGetSymbolAddress((void**)&pattn,g_attn);
    cudaGetSymbolAddress((void**)&ppre, g_pre);

    // 1) concat [x | prev_hidden]
    concat_xh_kernel<<<(Bsz * KQ) / 256, 256>>>(x, ph);

    // 2) pe projections (per-w bias rows for K/V gemms)
    pe_proj_kernel<<<dim3(Wwin, Hdim / 128), 128>>>(Wk_a, bk_a, Wv_a, bv_a);

    Epi e0 = {}; // zeroed

    // 3) q = elu(xh @ W_q^T + b_q)
    { Epi e = e0; e.bias = b_q; e.act = 1;
      launch_sgemm(pxh, W_q, pq, Bsz, Hdim, KQ, KQ, KQ, Hdim, e); }

    // 4) Q = q @ Wq_a^T + bq_a
    { Epi e = e0; e.bias = bq_a;
      launch_sgemm(pq, Wq_a, pQ, Bsz, Hdim, Hdim, Hdim, Hdim, Hdim, e); }

    // 5) K = elu(past_cells @ Wk_a[:, :H]^T + pe_k[w])   layout [W,B,H]
    { Epi e = e0; e.pe = ppek; e.act = 1;
      launch_sgemm(pcells, Wk_a, pK, Wwin * Bsz, Hdim, Hdim, Hdim, Hdim + Pdim, Hdim, e); }

    // 6) V likewise
    { Epi e = e0; e.pe = ppev; e.act = 1;
      launch_sgemm(pcells, Wv_a, pV, Wwin * Bsz, Hdim, Hdim, Hdim, Hdim + Pdim, Hdim, e); }

    // 7) attention -> ctx
    attention_kernel<<<Bsz, 1024>>>();

    // 8) attn = BN(elu(ctx @ Wo_a^T + bo_a))
    { Epi e = e0; e.bias = bo_a; e.act = 1;
      e.bn_g = bnag; e.bn_b = bnab; e.bn_m = bnam; e.bn_v = bnav;
      launch_sgemm(pctx, Wo_a, pattn, Bsz, Hdim, Hdim, Hdim, Hdim, Hdim, e); }

    // 9) pre = x@W_ih^T + b_ih + b_ac  (+= ph@W_hh^T) (+= attn@W_ac^T)
    { Epi e = e0; e.bias = b_ih; e.bias2 = b_ac;
      launch_sgemm(x, W_ih, ppre, Bsz, H4, IN_, IN_, IN_, H4, e); }
    { Epi e = e0; e.accumulate = 1;
      launch_sgemm(ph, W_hh, ppre, Bsz, H4, Hdim, Hdim, Hdim, H4, e); }
    { Epi e = e0; e.accumulate = 1;
      launch_sgemm(pattn, W_ac, ppre, Bsz, H4, Hdim, Hdim, Hdim, H4, e); }

    // 10) LSTM tail + post-BN -> out
    final_kernel<<<(Bsz * Hdim) / 256, 256>>>(pc, bnpg, bnpb, bnpm, bnpv, out);
}

// round 3
// speedup vs baseline: 3.2690x; 3.2690x over previous
#include <cuda_runtime.h>
#include <cuda_bf16.h>
#include <math.h>
#include <stdint.h>

#define Bsz   512
#define IN_   512
#define Hdim  1024
#define HEADS 16
#define DK    64
#define Wwin  32
#define Pdim  64
#define H4    4096
#define KQ    1536      // IN + H
#define EPSF  1e-5f

// ---------------- device scratch (static: no allocations allowed) ----------
__device__ float g_xh  [Bsz * KQ];
__device__ float g_q   [Bsz * Hdim];
__device__ float g_Q   [Bsz * Hdim];
__device__ float g_pek [Wwin * Hdim];
__device__ float g_pev [Wwin * Hdim];
__device__ float g_K   [(size_t)Wwin * Bsz * Hdim];
__device__ float g_V   [(size_t)Wwin * Bsz * Hdim];
__device__ float g_ctx [Bsz * Hdim];
__device__ float g_attn[Bsz * Hdim];
__device__ float g_pre [Bsz * H4];

// ---------------- helpers ----------------------------------------------------
__device__ __forceinline__ float rna_tf32(float x) {
    uint32_t u;
    asm("cvt.rna.tf32.f32 %0, %1;" : "=r"(u) : "f"(x));
    return __uint_as_float(u);
}
__device__ __forceinline__ float4 rna4(float4 v) {
    v.x = rna_tf32(v.x); v.y = rna_tf32(v.y); v.z = rna_tf32(v.z); v.w = rna_tf32(v.w);
    return v;
}
__device__ __forceinline__ float eluf(float x) { return x > 0.f ? x : expm1f(x); }

// warp-level tf32 tensor op: D(16x8) += A(16x8) * B(8x8)
__device__ __forceinline__ void mma16n8k8(float* d, const uint32_t* a, const uint32_t* b) {
    asm volatile(
        "mma.sync.aligned.m16n8k8.row.col.f32.tf32.tf32.f32 "
        "{%0,%1,%2,%3}, {%4,%5,%6,%7}, {%8,%9}, {%0,%1,%2,%3};"
        : "+f"(d[0]), "+f"(d[1]), "+f"(d[2]), "+f"(d[3])
        : "r"(a[0]), "r"(a[1]), "r"(a[2]), "r"(a[3]), "r"(b[0]), "r"(b[1]));
}

// ---------------- epilogue descriptor ---------------------------------------
struct Epi {
    const float* bias;
    const float* bias2;
    const float* pe;       // indexed by (bm>>9)*N + c
    int          act;
    const float* bn_g;
    const float* bn_b;
    const float* bn_m;
    const float* bn_v;
    int          accumulate;
};

// ---------------- tensor-core tf32 GEMM: C[M,N] = A[M,K] * B[N,K]^T ---------
// CTA tile 128x128x32, 256 threads (8 warps = 2m x 4n, warp tile 64x32).
#define TBM 128
#define TBN 128
#define TBK 32
#define SROW 36                       // smem row stride (floats): conflict-free frags
#define TC_SMEM (2 * (TBM * SROW + TBN * SROW) * 4)   // 73728 bytes

__global__ __launch_bounds__(256)
void mma_gemm(const float* __restrict__ A, const float* __restrict__ Bw,
              float* __restrict__ C,
              int M, int N, int K, int lda, int ldb, int ldc, Epi e)
{
    extern __shared__ float sm[];
    float* Asm = sm;                        // [2][128][36]
    float* Bsm = sm + 2 * TBM * SROW;       // [2][128][36]

    const int tid  = threadIdx.x;
    const int lane = tid & 31;
    const int wid  = tid >> 5;
    const int warpm = wid & 1;              // 0..1
    const int warpn = wid >> 1;             // 0..3
    const int bm = blockIdx.y * TBM;
    const int bn = blockIdx.x * TBN;

    // global load mapping: thread covers rows (tid>>3)+32j, float4 col group tid&7
    const int glr = tid >> 3;
    const int glc = (tid & 7) * 4;

    const float* Ag = A + (size_t)(bm + glr) * lda + glc;
    const float* Bg = Bw + (size_t)(bn + glr) * ldb + glc;

    float cacc[4][4][4];
    #pragma unroll
    for (int i = 0; i < 4; i++)
        #pragma unroll
        for (int j = 0; j < 4; j++)
            #pragma unroll
            for (int k = 0; k < 4; k++) cacc[i][j][k] = 0.f;

    float4 ra[4], rb[4];
    #pragma unroll
    for (int j = 0; j < 4; j++) {
        ra[j] = *(const float4*)(Ag + (size_t)(32 * j) * lda);
        rb[j] = *(const float4*)(Bg + (size_t)(32 * j) * ldb);
    }

    const int nT = K / TBK;
    for (int t = 0; t < nT; t++) {
        const int buf = t & 1;
        float* As = Asm + buf * TBM * SROW;
        float* Bs = Bsm + buf * TBN * SROW;

        #pragma unroll
        for (int j = 0; j < 4; j++) {
            *(float4*)(As + (glr + 32 * j) * SROW + glc) = rna4(ra[j]);
            *(float4*)(Bs + (glr + 32 * j) * SROW + glc) = rna4(rb[j]);
        }
        __syncthreads();

        if (t + 1 < nT) {
            #pragma unroll
            for (int j = 0; j < 4; j++) {
                ra[j] = *(const float4*)(Ag + (size_t)(32 * j) * lda + (t + 1) * TBK);
                rb[j] = *(const float4*)(Bg + (size_t)(32 * j) * ldb + (t + 1) * TBK);
            }
        }

        const uint32_t* As32 = (const uint32_t*)As;
        const uint32_t* Bs32 = (const uint32_t*)Bs;
        const int fr = lane >> 2;       // 0..7
        const int fc = lane & 3;        // 0..3

        #pragma unroll
        for (int ks = 0; ks < 4; ks++) {
            uint32_t af[4][4], bf[4][2];
            const int c = ks * 8 + fc;
            #pragma unroll
            for (int i = 0; i < 4; i++) {
                int r = warpm * 64 + i * 16 + fr;
                af[i][0] = As32[r * SROW + c];
                af[i][1] = As32[(r + 8) * SROW + c];
                af[i][2] = As32[r * SROW + c + 4];
                af[i][3] = As32[(r + 8) * SROW + c + 4];
            }
            #pragma unroll
            for (int j = 0; j < 4; j++) {
                int n = warpn * 32 + j * 8 + fr;
                bf[j][0] = Bs32[n * SROW + c];
                bf[j][1] = Bs32[n * SROW + c + 4];
            }
            #pragma unroll
            for (int i = 0; i < 4; i++)
                #pragma unroll
                for (int j = 0; j < 4; j++)
                    mma16n8k8(cacc[i][j], af[i], bf[j]);
        }
        __syncthreads();
    }

    // ---- epilogue: regs -> global (float2 stores, fused ops)
    const float* pe_row = e.pe ? (e.pe + (size_t)(bm >> 9) * N) : (const float*)0;
    const int fr = lane >> 2;
    const int fc = lane & 3;

    #pragma unroll
    for (int i = 0; i < 4; i++) {
        const int r0 = bm + warpm * 64 + i * 16 + fr;
        #pragma unroll
        for (int j = 0; j < 4; j++) {
            const int c0 = bn + warpn * 32 + j * 8 + 2 * fc;
            float v[4];
            #pragma unroll
            for (int k = 0; k < 4; k++) {
                float x = cacc[i][j][k];
                const int c = c0 + (k & 1);
                if (e.bias)  x += e.bias[c];
                if (e.bias2) x += e.bias2[c];
                if (pe_row)  x += pe_row[c];
                if (e.act)   x = eluf(x);
                if (e.bn_g)  x = (x - e.bn_m[c]) * e.bn_g[c] * rsqrtf(e.bn_v[c] + EPSF) + e.bn_b[c];
                v[k] = x;
            }
            float* p0 = C + (size_t)r0 * ldc + c0;
            float* p1 = C + (size_t)(r0 + 8) * ldc + c0;
            if (e.accumulate) {
                float2 o0 = *(float2*)p0, o1 = *(float2*)p1;
                v[0] += o0.x; v[1] += o0.y; v[2] += o1.x; v[3] += o1.y;
            }
            *(float2*)p0 = make_float2(v[0], v[1]);
            *(float2*)p1 = make_float2(v[2], v[3]);
        }
    }
}

// ---------------- small kernels ---------------------------------------------
__global__ void concat_xh_kernel(const float* __restrict__ x,
                                 const float* __restrict__ ph)
{
    int idx = blockIdx.x * blockDim.x + threadIdx.x;
    int r = idx / KQ, c = idx - r * KQ;
    g_xh[idx] = (c < IN_) ? x[(size_t)r * IN_ + c] : ph[(size_t)r * Hdim + (c - IN_)];
}

__global__ void pe_proj_kernel(const float* __restrict__ Wk, const float* __restrict__ bk,
                               const float* __restrict__ Wv, const float* __restrict__ bv)
{
    int w = blockIdx.x;
    int h = blockIdx.y * blockDim.x + threadIdx.x;
    const float* wkr = Wk + (size_t)h * (Hdim + Pdim) + Hdim;
    const float* wvr = Wv + (size_t)h * (Hdim + Pdim) + Hdim;
    float ak = bk[h], av = bv[h];
    const float c0 = logf(10000.0f) / (float)Pdim;
    #pragma unroll
    for (int i = 0; i < Pdim / 2; i++) {
        float div = expf(-(2.0f * i) * c0);
        float ang = (float)w * div;
        float s = sinf(ang), cc = cosf(ang);
        ak += s * wkr[2 * i] + cc * wkr[2 * i + 1];
        av += s * wvr[2 * i] + cc * wvr[2 * i + 1];
    }
    g_pek[w * Hdim + h] = ak;
    g_pev[w * Hdim + h] = av;
}

__global__ __launch_bounds__(1024)
void attention_kernel()
{
    int b   = blockIdx.x;
    int tid = threadIdx.x;
    int warp = tid >> 5, lane = tid & 31;

    __shared__ float qs[Hdim];
    __shared__ float S [HEADS][Wwin];
    __shared__ float ps[HEADS][Wwin];

    qs[tid] = g_Q[(size_t)b * Hdim + tid];
    __syncthreads();

    {
        const float* Krow = g_K + ((size_t)warp * Bsz + b) * Hdim;
        float acc[HEADS];
        #pragma unroll
        for (int h = 0; h < HEADS; h++) acc[h] = 0.f;
        #pragma unroll
        for (int j = 0; j < 32; j++) {
            int d = lane + 32 * j;
            acc[j >> 1] = fmaf(Krow[d], qs[d], acc[j >> 1]);
        }
        #pragma unroll
        for (int h = 0; h < HEADS; h++) {
            float v = acc[h];
            #pragma unroll
            for (int off = 16; off; off >>= 1)
                v += __shfl_down_sync(0xffffffffu, v, off);
            if (lane == 0) S[h][warp] = v * 0.125f;
        }
    }
    __syncthreads();

    if (warp < HEADS) {
        float s = S[warp][lane];
        float m = s;
        #pragma unroll
        for (int off = 16; off; off >>= 1)
            m = fmaxf(m, __shfl_xor_sync(0xffffffffu, m, off));
        float ev = expf(s - m);
        float sum = ev;
        #pragma unroll
        for (int off = 16; off; off >>= 1)
            sum += __shfl_xor_sync(0xffffffffu, sum, off);
        ps[warp][lane] = ev / sum;
    }
    __syncthreads();

    int h = tid >> 6;
    const float* Vb = g_V + (size_t)b * Hdim + tid;
    float acc = 0.f;
    #pragma unroll
    for (int w = 0; w < Wwin; w++)
        acc = fmaf(ps[h][w], Vb[(size_t)w * Bsz * Hdim], acc);
    g_ctx[(size_t)b * Hdim + tid] = acc;
}

__global__ void final_kernel(const float* __restrict__ pcell,
                             const float* __restrict__ gmm, const float* __restrict__ bb,
                             const float* __restrict__ mm, const float* __restrict__ vv,
                             float* __restrict__ out)
{
    int idx = blockIdx.x * blockDim.x + threadIdx.x;
    int r = idx >> 10, c = idx & 1023;
    const float* p = g_pre + (size_t)r * H4;
    float iv = tanhf(p[c]);
    float f  = 1.f / (1.f + expf(-p[1024 + c]));
    float ig = 1.f / (1.f + expf(-p[2048 + c]));
    float o  = 1.f / (1.f + expf(-p[3072 + c]));
    float cell = iv * ig + pcell[idx] * f;
    float e = eluf(cell);
    out[idx] = (o * e - mm[c]) * gmm[c] * rsqrtf(vv[c] + EPSF) + bb[c];
}

// ---------------- host --------------------------------------------------------
static void launch_tc(const float* A, const float* Bw, float* C,
                      int M, int N, int K, int lda, int ldb, int ldc, Epi e)
{
    dim3 grid(N / TBN, M / TBM);
    mma_gemm<<<grid, 256, TC_SMEM>>>(A, Bw, C, M, N, K, lda, ldb, ldc, e);
}

extern "C" void kernel_launch(void* const* d_in, const int* in_sizes, int n_in,
                              void* d_out, int out_size)
{
    const float* x      = (const float*)d_in[0];
    const float* ph     = (const float*)d_in[1];
    const float* pc     = (const float*)d_in[2];
    const float* pcells = (const float*)d_in[3];
    const float* W_ih   = (const float*)d_in[4];
    const float* b_ih   = (const float*)d_in[5];
    const float* W_hh   = (const float*)d_in[6];
    const float* W_q    = (const float*)d_in[7];
    const float* b_q    = (const float*)d_in[8];
    const float* W_ac   = (const float*)d_in[9];
    const float* b_ac   = (const float*)d_in[10];
    const float* Wq_a   = (const float*)d_in[11];
    const float* bq_a   = (const float*)d_in[12];
    const float* Wk_a   = (const float*)d_in[13];
    const float* bk_a   = (const float*)d_in[14];
    const float* Wv_a   = (const float*)d_in[15];
    const float* bv_a   = (const float*)d_in[16];
    const float* Wo_a   = (const float*)d_in[17];
    const float* bo_a   = (const float*)d_in[18];
    const float* bnag   = (const float*)d_in[19];
    const float* bnab   = (const float*)d_in[20];
    const float* bnam   = (const float*)d_in[21];
    const float* bnav   = (const float*)d_in[22];
    const float* bnpg   = (const float*)d_in[23];
    const float* bnpb   = (const float*)d_in[24];
    const float* bnpm   = (const float*)d_in[25];
    const float* bnpv   = (const float*)d_in[26];
    float* out = (float*)d_out;

    cudaFuncSetAttribute(mma_gemm, cudaFuncAttributeMaxDynamicSharedMemorySize, TC_SMEM);

    float *pxh, *pq, *pQ, *ppek, *ppev, *pK, *pV, *pctx, *pattn, *ppre;
    cudaGetSymbolAddress((void**)&pxh,  g_xh);
    cudaGetSymbolAddress((void**)&pq,   g_q);
    cudaGetSymbolAddress((void**)&pQ,   g_Q);
    cudaGetSymbolAddress((void**)&ppek, g_pek);
    cudaGetSymbolAddress((void**)&ppev, g_pev);
    cudaGetSymbolAddress((void**)&pK,   g_K);
    cudaGetSymbolAddress((void**)&pV,   g_V);
    cudaGetSymbolAddress((void**)&pctx, g_ctx);
    cudaGetSymbolAddress((void**)&pattn,g_attn);
    cudaGetSymbolAddress((void**)&ppre, g_pre);

    // 1) concat [x | prev_hidden]
    concat_xh_kernel<<<(Bsz * KQ) / 256, 256>>>(x, ph);

    // 2) pe projections (exact fp32 per-w bias rows for K/V gemms)
    pe_proj_kernel<<<dim3(Wwin, Hdim / 128), 128>>>(Wk_a, bk_a, Wv_a, bv_a);

    Epi e0 = {};

    // 3) q = elu(xh @ W_q^T + b_q)
    { Epi e = e0; e.bias = b_q; e.act = 1;
      launch_tc(pxh, W_q, pq, Bsz, Hdim, KQ, KQ, KQ, Hdim, e); }

    // 4) Q = q @ Wq_a^T + bq_a
    { Epi e = e0; e.bias = bq_a;
      launch_tc(pq, Wq_a, pQ, Bsz, Hdim, Hdim, Hdim, Hdim, Hdim, e); }

    // 5) K = elu(past_cells @ Wk_a[:, :H]^T + pe_k[w])   layout [W,B,H]
    { Epi e = e0; e.pe = ppek; e.act = 1;
      launch_tc(pcells, Wk_a, pK, Wwin * Bsz, Hdim, Hdim, Hdim, Hdim + Pdim, Hdim, e); }

    // 6) V likewise
    { Epi e = e0; e.pe = ppev; e.act = 1;
      launch_tc(pcells, Wv_a, pV, Wwin * Bsz, Hdim, Hdim, Hdim, Hdim + Pdim, Hdim, e); }

    // 7) attention -> ctx
    attention_kernel<<<Bsz, 1024>>>();

    // 8) attn = BN(elu(ctx @ Wo_a^T + bo_a))
    { Epi e = e0; e.bias = bo_a; e.act = 1;
      e.bn_g = bnag; e.bn_b = bnab; e.bn_m = bnam; e.bn_v = bnav;
      launch_tc(pctx, Wo_a, pattn, Bsz, Hdim, Hdim, Hdim, Hdim, Hdim, e); }

    // 9) pre = x@W_ih^T + b_ih + b_ac  (+= ph@W_hh^T) (+= attn@W_ac^T)
    { Epi e = e0; e.bias = b_ih; e.bias2 = b_ac;
      launch_tc(pxh, W_ih, ppre, Bsz, H4, IN_, KQ, IN_, H4, e); }
    { Epi e = e0; e.accumulate = 1;
      launch_tc(pxh + IN_, W_hh, ppre, Bsz, H4, Hdim, KQ, Hdim, H4, e); }
    { Epi e = e0; e.accumulate = 1;
      launch_tc(pattn, W_ac, ppre, Bsz, H4, Hdim, Hdim, Hdim, H4, e); }

    // 10) LSTM tail + post-BN -> out
    final_kernel<<<(Bsz * Hdim) / 256, 256>>>(pc, bnpg, bnpb, bnpm, bnpv, out);
}

// round 4
// speedup vs baseline: 4.1425x; 1.2672x over previous
#include <cuda_runtime.h>
#include <cuda_bf16.h>
#include <math.h>
#include <stdint.h>

#define Bsz   512
#define IN_   512
#define Hdim  1024
#define HEADS 16
#define DK    64
#define Wwin  32
#define Pdim  64
#define H4    4096
#define KQ    1536
#define KPRE  2560      // IN + H + H (fused pre-activation K)
#define EPSF  1e-5f

// ---------------- device scratch (static: no allocations allowed) ----------
__device__ float g_xh2 [Bsz * KPRE];                  // [x | ph | attn], tf32-rounded
__device__ float g_q   [Bsz * Hdim];                  // rounded
__device__ float g_Q   [Bsz * Hdim];
__device__ float g_pek [Wwin * Hdim];
__device__ float g_pev [Wwin * Hdim];
__device__ float g_K   [(size_t)Wwin * Bsz * Hdim];
__device__ float g_V   [(size_t)Wwin * Bsz * Hdim];
__device__ float g_ctx [Bsz * Hdim];                  // rounded
__device__ float g_pre [Bsz * H4];
__device__ float g_pcT [(size_t)Wwin * Bsz * Hdim];   // rounded past_cells
__device__ float g_WqT [Hdim * KQ];
__device__ float g_WqaT[Hdim * Hdim];
__device__ float g_WkT [Hdim * (Hdim + Pdim)];
__device__ float g_WvT [Hdim * (Hdim + Pdim)];
__device__ float g_WoT [Hdim * Hdim];
__device__ float g_Wpre[(size_t)H4 * KPRE];           // [W_ih | W_hh | W_ac] rounded

// ---------------- helpers ----------------------------------------------------
__device__ __forceinline__ uint32_t smem_u32(const void* p) {
    uint32_t a;
    asm("{ .reg .u64 t; cvta.to.shared.u64 t, %1; cvt.u32.u64 %0, t; }" : "=r"(a) : "l"(p));
    return a;
}
__device__ __forceinline__ float rna_tf32(float x) {
    uint32_t u;
    asm("cvt.rna.tf32.f32 %0, %1;" : "=r"(u) : "f"(x));
    return __uint_as_float(u);
}
__device__ __forceinline__ float4 rna4(float4 v) {
    v.x = rna_tf32(v.x); v.y = rna_tf32(v.y); v.z = rna_tf32(v.z); v.w = rna_tf32(v.w);
    return v;
}
__device__ __forceinline__ float eluf(float x) { return x > 0.f ? x : expm1f(x); }

__device__ __forceinline__ void cp16(uint32_t s, const float* g) {
    asm volatile("cp.async.cg.shared.global [%0], [%1], 16;" :: "r"(s), "l"(g));
}
__device__ __forceinline__ void cp_commit() { asm volatile("cp.async.commit_group;" ::: "memory"); }
template<int N> __device__ __forceinline__ void cp_wait() {
    asm volatile("cp.async.wait_group %0;" :: "n"(N) : "memory");
}

__device__ __forceinline__ void mma16n8k8(float* d, const uint32_t* a, const uint32_t* b) {
    asm volatile(
        "mma.sync.aligned.m16n8k8.row.col.f32.tf32.tf32.f32 "
        "{%0,%1,%2,%3}, {%4,%5,%6,%7}, {%8,%9}, {%0,%1,%2,%3};"
        : "+f"(d[0]), "+f"(d[1]), "+f"(d[2]), "+f"(d[3])
        : "r"(a[0]), "r"(a[1]), "r"(a[2]), "r"(a[3]), "r"(b[0]), "r"(b[1]));
}

// ---------------- epilogue descriptor ---------------------------------------
struct Epi {
    const float* bias;
    const float* bias2;
    const float* pe;       // indexed by (row>>9)*N + c
    int          act;
    const float* bn_g;
    const float* bn_b;
    const float* bn_m;
    const float* bn_v;
};

// ---------------- cp.async pipelined tf32 GEMM: C[M,N] = A*B^T --------------
// CTA tile (MI*32) x 128 x 32, 256 threads, 8 warps (2m x 4n), 3-stage pipeline.
// Operands MUST be pre-rounded to tf32 (RNA).
template<int MI, int ROUND>
__global__ __launch_bounds__(256, 2)
void tc_gemm(const float* __restrict__ A, const float* __restrict__ Bw,
             float* __restrict__ C,
             int M, int N, int K, int lda, int ldb, int ldc, Epi e)
{
    constexpr int TBM = MI * 32;
    constexpr int SROW = 36;
    constexpr int STG = (TBM + 128) * SROW;   // floats per pipeline stage

    extern __shared__ float sm[];
    const uint32_t smb = smem_u32(sm);

    const int tid  = threadIdx.x;
    const int lane = tid & 31;
    const int wid  = tid >> 5;
    const int warpm = wid & 1;
    const int warpn = wid >> 1;
    const int bm = blockIdx.y * TBM;
    const int bn = blockIdx.x * 128;
    const int glr = tid >> 3;
    const int glc = (tid & 7) * 4;
    const int fr = lane >> 2;
    const int fc = lane & 3;

    const float* Abase = A + (size_t)(bm + glr) * lda + glc;
    const float* Bbase = Bw + (size_t)(bn + glr) * ldb + glc;
    const uint32_t dA0 = smb + (uint32_t)(glr * SROW + glc) * 4;
    const uint32_t dB0 = smb + (uint32_t)(TBM * SROW + glr * SROW + glc) * 4;

    const int nT = K >> 5;

    auto issue = [&](int s, int t) {
        const float* ga = Abase + t * 32;
        const float* gb = Bbase + t * 32;
        const uint32_t so = (uint32_t)(s * STG) * 4;
        #pragma unroll
        for (int j = 0; j < MI; j++)
            cp16(dA0 + so + (uint32_t)(j * 32 * SROW) * 4, ga + (size_t)(32 * j) * lda);
        #pragma unroll
        for (int j = 0; j < 4; j++)
            cp16(dB0 + so + (uint32_t)(j * 32 * SROW) * 4, gb + (size_t)(32 * j) * ldb);
    };

    float acc[MI][4][4];
    #pragma unroll
    for (int i = 0; i < MI; i++)
        #pragma unroll
        for (int j = 0; j < 4; j++)
            #pragma unroll
            for (int k = 0; k < 4; k++) acc[i][j][k] = 0.f;

    issue(0, 0); cp_commit();
    issue(1, 1); cp_commit();

    for (int t = 0; t < nT; t++) {
        cp_wait<1>();
        __syncthreads();
        if (t + 2 < nT) issue((t + 2) % 3, t + 2);
        cp_commit();

        const float* As = sm + (t % 3) * STG;
        const uint32_t* As32 = (const uint32_t*)As;
        const uint32_t* Bs32 = (const uint32_t*)(As + TBM * SROW);

        #pragma unroll
        for (int ks = 0; ks < 4; ks++) {
            const int c = ks * 8 + fc;
            uint32_t af[MI][4], bf[4][2];
            #pragma unroll
            for (int i = 0; i < MI; i++) {
                int r = warpm * (MI * 16) + i * 16 + fr;
                af[i][0] = As32[r * SROW + c];
                af[i][1] = As32[(r + 8) * SROW + c];
                af[i][2] = As32[r * SROW + c + 4];
                af[i][3] = As32[(r + 8) * SROW + c + 4];
            }
            #pragma unroll
            for (int j = 0; j < 4; j++) {
                int n = warpn * 32 + j * 8 + fr;
                bf[j][0] = Bs32[n * SROW + c];
                bf[j][1] = Bs32[n * SROW + c + 4];
            }
            #pragma unroll
            for (int i = 0; i < MI; i++)
                #pragma unroll
                for (int j = 0; j < 4; j++)
                    mma16n8k8(acc[i][j], af[i], bf[j]);
        }
    }

    // ---- epilogue: regs -> global (float2 stores, fused ops)
    const float* pe_row = e.pe ? (e.pe + (size_t)(bm >> 9) * N) : (const float*)0;

    #pragma unroll
    for (int i = 0; i < MI; i++) {
        const int r0 = bm + warpm * (MI * 16) + i * 16 + fr;
        #pragma unroll
        for (int j = 0; j < 4; j++) {
            const int c0 = bn + warpn * 32 + j * 8 + 2 * fc;
            float v[4];
            #pragma unroll
            for (int k = 0; k < 4; k++) {
                float x = acc[i][j][k];
                const int c = c0 + (k & 1);
                if (e.bias)  x += e.bias[c];
                if (e.bias2) x += e.bias2[c];
                if (pe_row)  x += pe_row[c];
                if (e.act)   x = eluf(x);
                if (e.bn_g)  x = (x - e.bn_m[c]) * e.bn_g[c] * rsqrtf(e.bn_v[c] + EPSF) + e.bn_b[c];
                if (ROUND)   x = rna_tf32(x);
                v[k] = x;
            }
            float* p0 = C + (size_t)r0 * ldc + c0;
            float* p1 = C + (size_t)(r0 + 8) * ldc + c0;
            *(float2*)p0 = make_float2(v[0], v[1]);
            *(float2*)p1 = make_float2(v[2], v[3]);
        }
    }
}

// ---------------- preconversion / small kernels -----------------------------
__global__ void rna_copy4(const float4* __restrict__ src, float4* __restrict__ dst, int n4)
{
    int i = blockIdx.x * blockDim.x + threadIdx.x;
    if (i < n4) dst[i] = rna4(src[i]);
}

__global__ void build_wpre(const float* __restrict__ Wih, const float* __restrict__ Whh,
                           const float* __restrict__ Wac)
{
    int idx = blockIdx.x * blockDim.x + threadIdx.x;   // over 4096*640 float4s
    int row = idx / 640, c4 = idx - row * 640;
    int c = c4 * 4;
    const float* src;
    if (c < 512)       src = Wih + (size_t)row * 512 + c;
    else if (c < 1536) src = Whh + (size_t)row * 1024 + (c - 512);
    else               src = Wac + (size_t)row * 1024 + (c - 1536);
    float4 v = *(const float4*)src;
    *(float4*)(g_Wpre + (size_t)row * KPRE + c) = rna4(v);
}

__global__ void concat_xh2(const float* __restrict__ x, const float* __restrict__ ph)
{
    int idx = blockIdx.x * blockDim.x + threadIdx.x;   // over 512*384 float4s
    int row = idx / 384, c4 = idx - row * 384;
    int c = c4 * 4;
    float4 v = (c < 512) ? *(const float4*)(x + (size_t)row * 512 + c)
                         : *(const float4*)(ph + (size_t)row * 1024 + (c - 512));
    *(float4*)(g_xh2 + (size_t)row * KPRE + c) = rna4(v);
}

__global__ void pe_proj_kernel(const float* __restrict__ Wk, const float* __restrict__ bk,
                               const float* __restrict__ Wv, const float* __restrict__ bv)
{
    int w = blockIdx.x;
    int h = blockIdx.y * blockDim.x + threadIdx.x;
    const float* wkr = Wk + (size_t)h * (Hdim + Pdim) + Hdim;
    const float* wvr = Wv + (size_t)h * (Hdim + Pdim) + Hdim;
    float ak = bk[h], av = bv[h];
    const float c0 = logf(10000.0f) / (float)Pdim;
    #pragma unroll
    for (int i = 0; i < Pdim / 2; i++) {
        float div = expf(-(2.0f * i) * c0);
        float ang = (float)w * div;
        float s = sinf(ang), cc = cosf(ang);
        ak += s * wkr[2 * i] + cc * wkr[2 * i + 1];
        av += s * wvr[2 * i] + cc * wvr[2 * i + 1];
    }
    g_pek[w * Hdim + h] = ak;
    g_pev[w * Hdim + h] = av;
}

__global__ __launch_bounds__(1024)
void attention_kernel()
{
    int b   = blockIdx.x;
    int tid = threadIdx.x;
    int warp = tid >> 5, lane = tid & 31;

    __shared__ float qs[Hdim];
    __shared__ float S [HEADS][Wwin];
    __shared__ float ps[HEADS][Wwin];

    qs[tid] = g_Q[(size_t)b * Hdim + tid];
    __syncthreads();

    {
        const float* Krow = g_K + ((size_t)warp * Bsz + b) * Hdim;
        float acc[HEADS];
        #pragma unroll
        for (int h = 0; h < HEADS; h++) acc[h] = 0.f;
        #pragma unroll
        for (int j = 0; j < 32; j++) {
            int d = lane + 32 * j;
            acc[j >> 1] = fmaf(Krow[d], qs[d], acc[j >> 1]);
        }
        #pragma unroll
        for (int h = 0; h < HEADS; h++) {
            float v = acc[h];
            #pragma unroll
            for (int off = 16; off; off >>= 1)
                v += __shfl_down_sync(0xffffffffu, v, off);
            if (lane == 0) S[h][warp] = v * 0.125f;
        }
    }
    __syncthreads();

    if (warp < HEADS) {
        float s = S[warp][lane];
        float m = s;
        #pragma unroll
        for (int off = 16; off; off >>= 1)
            m = fmaxf(m, __shfl_xor_sync(0xffffffffu, m, off));
        float ev = expf(s - m);
        float sum = ev;
        #pragma unroll
        for (int off = 16; off; off >>= 1)
            sum += __shfl_xor_sync(0xffffffffu, sum, off);
        ps[warp][lane] = ev / sum;
    }
    __syncthreads();

    int h = tid >> 6;
    const float* Vb = g_V + (size_t)b * Hdim + tid;
    float acc = 0.f;
    #pragma unroll
    for (int w = 0; w < Wwin; w++)
        acc = fmaf(ps[h][w], Vb[(size_t)w * Bsz * Hdim], acc);
    g_ctx[(size_t)b * Hdim + tid] = rna_tf32(acc);
}

__global__ void final_kernel(const float* __restrict__ pcell,
                             const float* __restrict__ gmm, const float* __restrict__ bb,
                             const float* __restrict__ mm, const float* __restrict__ vv,
                             float* __restrict__ out)
{
    int idx = blockIdx.x * blockDim.x + threadIdx.x;
    int r = idx >> 10, c = idx & 1023;
    const float* p = g_pre + (size_t)r * H4;
    float iv = tanhf(p[c]);
    float f  = 1.f / (1.f + expf(-p[1024 + c]));
    float ig = 1.f / (1.f + expf(-p[2048 + c]));
    float o  = 1.f / (1.f + expf(-p[3072 + c]));
    float cell = iv * ig + pcell[idx] * f;
    float e = eluf(cell);
    out[idx] = (o * e - mm[c]) * gmm[c] * rsqrtf(vv[c] + EPSF) + bb[c];
}

// ---------------- host --------------------------------------------------------
#define SMEM_MI2 ((64 + 128) * 36 * 3 * 4)
#define SMEM_MI4 ((128 + 128) * 36 * 3 * 4)

static void rna_arr(const float* src, float* dst, size_t n)
{
    int n4 = (int)(n / 4);
    rna_copy4<<<(n4 + 255) / 256, 256>>>((const float4*)src, (float4*)dst, n4);
}

extern "C" void kernel_launch(void* const* d_in, const int* in_sizes, int n_in,
                              void* d_out, int out_size)
{
    const float* x      = (const float*)d_in[0];
    const float* ph     = (const float*)d_in[1];
    const float* pc     = (const float*)d_in[2];
    const float* pcells = (const float*)d_in[3];
    const float* W_ih   = (const float*)d_in[4];
    const float* b_ih   = (const float*)d_in[5];
    const float* W_hh   = (const float*)d_in[6];
    const float* W_q    = (const float*)d_in[7];
    const float* b_q    = (const float*)d_in[8];
    const float* W_ac   = (const float*)d_in[9];
    const float* b_ac   = (const float*)d_in[10];
    const float* Wq_a   = (const float*)d_in[11];
    const float* bq_a   = (const float*)d_in[12];
    const float* Wk_a   = (const float*)d_in[13];
    const float* bk_a   = (const float*)d_in[14];
    const float* Wv_a   = (const float*)d_in[15];
    const float* bv_a   = (const float*)d_in[16];
    const float* Wo_a   = (const float*)d_in[17];
    const float* bo_a   = (const float*)d_in[18];
    const float* bnag   = (const float*)d_in[19];
    const float* bnab   = (const float*)d_in[20];
    const float* bnam   = (const float*)d_in[21];
    const float* bnav   = (const float*)d_in[22];
    const float* bnpg   = (const float*)d_in[23];
    const float* bnpb   = (const float*)d_in[24];
    const float* bnpm   = (const float*)d_in[25];
    const float* bnpv   = (const float*)d_in[26];
    float* out = (float*)d_out;

    cudaFuncSetAttribute(tc_gemm<2,0>, cudaFuncAttributeMaxDynamicSharedMemorySize, SMEM_MI2);
    cudaFuncSetAttribute(tc_gemm<2,1>, cudaFuncAttributeMaxDynamicSharedMemorySize, SMEM_MI2);
    cudaFuncSetAttribute(tc_gemm<4,0>, cudaFuncAttributeMaxDynamicSharedMemorySize, SMEM_MI4);

    float *pxh2, *pq, *pQ, *ppek, *ppev, *pK, *pV, *pctx, *ppre;
    float *ppcT, *pWqT, *pWqaT, *pWkT, *pWvT, *pWoT, *pWpre;
    cudaGetSymbolAddress((void**)&pxh2, g_xh2);
    cudaGetSymbolAddress((void**)&pq,   g_q);
    cudaGetSymbolAddress((void**)&pQ,   g_Q);
    cudaGetSymbolAddress((void**)&ppek, g_pek);
    cudaGetSymbolAddress((void**)&ppev, g_pev);
    cudaGetSymbolAddress((void**)&pK,   g_K);
    cudaGetSymbolAddress((void**)&pV,   g_V);
    cudaGetSymbolAddress((void**)&pctx, g_ctx);
    cudaGetSymbolAddress((void**)&ppre, g_pre);
    cudaGetSymbolAddress((void**)&ppcT, g_pcT);
    cudaGetSymbolAddress((void**)&pWqT, g_WqT);
    cudaGetSymbolAddress((void**)&pWqaT,g_WqaT);
    cudaGetSymbolAddress((void**)&pWkT, g_WkT);
    cudaGetSymbolAddress((void**)&pWvT, g_WvT);
    cudaGetSymbolAddress((void**)&pWoT, g_WoT);
    cudaGetSymbolAddress((void**)&pWpre,g_Wpre);

    // ---- preconversion (RNA tf32 rounding of all GEMM operands)
    concat_xh2<<<(Bsz * 384 + 255) / 256, 256>>>(x, ph);
    pe_proj_kernel<<<dim3(Wwin, Hdim / 128), 128>>>(Wk_a, bk_a, Wv_a, bv_a);
    rna_arr(pcells, ppcT, (size_t)Wwin * Bsz * Hdim);
    rna_arr(W_q,  pWqT,  (size_t)Hdim * KQ);
    rna_arr(Wq_a, pWqaT, (size_t)Hdim * Hdim);
    rna_arr(Wk_a, pWkT,  (size_t)Hdim * (Hdim + Pdim));
    rna_arr(Wv_a, pWvT,  (size_t)Hdim * (Hdim + Pdim));
    rna_arr(Wo_a, pWoT,  (size_t)Hdim * Hdim);
    build_wpre<<<(H4 * 640 + 255) / 256, 256>>>(W_ih, W_hh, W_ac);

    Epi e0 = {};

    // q = elu(xh @ W_q^T + b_q)  (rounded out)
    { Epi e = e0; e.bias = b_q; e.act = 1;
      tc_gemm<2,1><<<dim3(Hdim/128, Bsz/64), 256, SMEM_MI2>>>(
          pxh2, pWqT, pq, Bsz, Hdim, KQ, KPRE, KQ, Hdim, e); }

    // Q = q @ Wq_a^T + bq_a
    { Epi e = e0; e.bias = bq_a;
      tc_gemm<2,0><<<dim3(Hdim/128, Bsz/64), 256, SMEM_MI2>>>(
          pq, pWqaT, pQ, Bsz, Hdim, Hdim, Hdim, Hdim, Hdim, e); }

    // K = elu(pcells @ Wk_a[:, :H]^T + pe_k[w])   layout [W,B,H]
    { Epi e = e0; e.pe = ppek; e.act = 1;
      tc_gemm<4,0><<<dim3(Hdim/128, (Wwin*Bsz)/128), 256, SMEM_MI4>>>(
          ppcT, pWkT, pK, Wwin*Bsz, Hdim, Hdim, Hdim, Hdim + Pdim, Hdim, e); }

    // V likewise
    { Epi e = e0; e.pe = ppev; e.act = 1;
      tc_gemm<4,0><<<dim3(Hdim/128, (Wwin*Bsz)/128), 256, SMEM_MI4>>>(
          ppcT, pWvT, pV, Wwin*Bsz, Hdim, Hdim, Hdim, Hdim + Pdim, Hdim, e); }

    // attention -> ctx (rounded out)
    attention_kernel<<<Bsz, 1024>>>();

    // attn = BN(elu(ctx @ Wo_a^T + bo_a))  written into xh2 cols [1536, 2560), rounded
    { Epi e = e0; e.bias = bo_a; e.act = 1;
      e.bn_g = bnag; e.bn_b = bnab; e.bn_m = bnam; e.bn_v = bnav;
      tc_gemm<2,1><<<dim3(Hdim/128, Bsz/64), 256, SMEM_MI2>>>(
          pctx, pWoT, pxh2 + KQ, Bsz, Hdim, Hdim, Hdim, Hdim, KPRE, e); }

    // pre = [x|ph|attn] @ [W_ih|W_hh|W_ac]^T + b_ih + b_ac   (single fused GEMM)
    { Epi e = e0; e.bias = b_ih; e.bias2 = b_ac;
      tc_gemm<2,0><<<dim3(H4/128, Bsz/64), 256, SMEM_MI2>>>(
          pxh2, pWpre, ppre, Bsz, H4, KPRE, KPRE, KPRE, H4, e); }

    // LSTM tail + post-BN -> out
    final_kernel<<<(Bsz * Hdim) / 256, 256>>>(pc, bnpg, bnpb, bnpm, bnpv, out);
}

// round 5
// speedup vs baseline: 6.5552x; 1.5824x over previous
#include <cuda_runtime.h>
#include <cuda_fp16.h>
#include <math.h>
#include <stdint.h>

#define Bsz   512
#define IN_   512
#define Hdim  1024
#define HEADS 16
#define DK    64
#define Wwin  32
#define Pdim  64
#define H4    4096
#define KQ    1536
#define KPRE  2560
#define NKV   2048
#define EPSF  1e-5f

// ---------------- device scratch --------------------------------------------
__device__ __half g_xh2h[Bsz * KPRE];                   // [x | ph | attn] fp16
__device__ __half g_qh  [Bsz * Hdim];
__device__ float  g_Q   [Bsz * Hdim];
__device__ float  g_pekv[Wwin * NKV];                   // f32 pe bias rows [w][2048]
__device__ __half g_KV  [(size_t)Wwin * Bsz * NKV];     // [W,B,{K|V}]
__device__ __half g_ctxh[Bsz * Hdim];
__device__ float  g_pre [Bsz * H4];
__device__ __half g_pch [(size_t)Wwin * Bsz * Hdim];    // fp16 past_cells
__device__ __half g_Wqh [Hdim * KQ];
__device__ __half g_Wqah[Hdim * Hdim];
__device__ __half g_Wkvh[(size_t)NKV * Hdim];           // [Wk ; Wv] (:, :H)
__device__ __half g_Woh [Hdim * Hdim];
__device__ __half g_Wpreh[(size_t)H4 * KPRE];           // [W_ih | W_hh | W_ac]

// ---------------- helpers ----------------------------------------------------
__device__ __forceinline__ uint32_t smem_u32(const void* p) {
    uint32_t a;
    asm("{ .reg .u64 t; cvta.to.shared.u64 t, %1; cvt.u32.u64 %0, t; }" : "=r"(a) : "l"(p));
    return a;
}
__device__ __forceinline__ float eluf(float x) { return x > 0.f ? x : expm1f(x); }

__device__ __forceinline__ void cp16(uint32_t s, const void* g) {
    asm volatile("cp.async.cg.shared.global [%0], [%1], 16;" :: "r"(s), "l"(g));
}
__device__ __forceinline__ void cp_commit() { asm volatile("cp.async.commit_group;" ::: "memory"); }
template<int N> __device__ __forceinline__ void cp_wait() {
    asm volatile("cp.async.wait_group %0;" :: "n"(N) : "memory");
}
__device__ __forceinline__ void ldsm_x4(uint32_t& r0, uint32_t& r1, uint32_t& r2, uint32_t& r3, uint32_t a) {
    asm volatile("ldmatrix.sync.aligned.m8n8.x4.shared.b16 {%0,%1,%2,%3}, [%4];"
                 : "=r"(r0), "=r"(r1), "=r"(r2), "=r"(r3) : "r"(a));
}
__device__ __forceinline__ void mma16816(float* d, const uint32_t* a, const uint32_t* b) {
    asm volatile("mma.sync.aligned.m16n8k16.row.col.f32.f16.f16.f32 "
        "{%0,%1,%2,%3}, {%4,%5,%6,%7}, {%8,%9}, {%0,%1,%2,%3};"
        : "+f"(d[0]), "+f"(d[1]), "+f"(d[2]), "+f"(d[3])
        : "r"(a[0]), "r"(a[1]), "r"(a[2]), "r"(a[3]), "r"(b[0]), "r"(b[1]));
}

// ---------------- epilogue descriptor ---------------------------------------
struct Epi {
    const float* bias;
    const float* bias2;
    const float* pe;       // indexed by (row>>9)*N + c
    int          act;
    const float* bn_g;
    const float* bn_b;
    const float* bn_m;
    const float* bn_v;
};

// ---------------- fp16 tensor GEMM: C[M,N] = A*B^T ---------------------------
// CTA tile (MI*32) x 128 x 32, 256 threads, 8 warps (2m x 4n), 3-stage cp.async.
#define SROW 40   // halves per smem row (80B: ldmatrix conflict-free)

template<int MI, int HOUT>
__global__ __launch_bounds__(256, 2)
void hgemm(const __half* __restrict__ A, const __half* __restrict__ Bw,
           void* __restrict__ Cv,
           int M, int N, int K, int lda, int ldb, int ldc, Epi e)
{
    constexpr int TBM = MI * 32;
    constexpr int STG = (TBM + 128) * SROW;   // halves per stage

    extern __shared__ __half sm[];
    const uint32_t smb = smem_u32(sm);

    const int tid  = threadIdx.x;
    const int lane = tid & 31;
    const int wid  = tid >> 5;
    const int warpm = wid & 1;
    const int warpn = wid >> 1;
    const int bm = blockIdx.y * TBM;
    const int bn = blockIdx.x * 128;
    const int fr = lane >> 2;
    const int fc = lane & 3;

    // cp.async mapping: thread -> (row = tid/4 [+64..], 8-half chunk tid%4)
    const int ar = tid >> 2;
    const int ac = (tid & 3) * 8;

    const __half* Abase = A + (size_t)(bm + ar) * lda + ac;
    const __half* Bbase = Bw + (size_t)(bn + ar) * ldb + ac;
    const uint32_t dA0 = smb + (uint32_t)(ar * SROW + ac) * 2;
    const uint32_t dB0 = smb + (uint32_t)((TBM + ar) * SROW + ac) * 2;

    const int nT = K >> 5;

    auto issue = [&](int s, int t) {
        const uint32_t so = (uint32_t)(s * STG) * 2;
        #pragma unroll
        for (int j = 0; j < MI / 2; j++)
            cp16(dA0 + so + (uint32_t)(j * 64 * SROW) * 2,
                 Abase + (size_t)(64 * j) * lda + t * 32);
        #pragma unroll
        for (int j = 0; j < 2; j++)
            cp16(dB0 + so + (uint32_t)(j * 64 * SROW) * 2,
                 Bbase + (size_t)(64 * j) * ldb + t * 32);
    };

    float acc[MI][4][4];
    #pragma unroll
    for (int i = 0; i < MI; i++)
        #pragma unroll
        for (int j = 0; j < 4; j++)
            #pragma unroll
            for (int k = 0; k < 4; k++) acc[i][j][k] = 0.f;

    issue(0, 0); cp_commit();
    issue(1, 1); cp_commit();

    // ldmatrix lane addressing
    const int a_r = ((lane >> 3) & 1) * 8 + (lane & 7);   // row within 16
    const int a_c = (lane >> 4) * 8;                      // k-half within 16
    const int b_r = (lane >> 4) * 8 + (lane & 7);         // n within pair of tiles
    const int b_c = ((lane >> 3) & 1) * 8;                // k-half within 16

    for (int t = 0; t < nT; t++) {
        cp_wait<1>();
        __syncthreads();
        if (t + 2 < nT) issue((t + 2) % 3, t + 2);
        cp_commit();

        const uint32_t sA = smb + (uint32_t)((t % 3) * STG) * 2;
        const uint32_t sB = sA + (uint32_t)(TBM * SROW) * 2;

        #pragma unroll
        for (int ks = 0; ks < 2; ks++) {
            uint32_t af[MI][4], bf[4][2];
            #pragma unroll
            for (int i = 0; i < MI; i++) {
                int r = warpm * (MI * 16) + i * 16 + a_r;
                int c = ks * 16 + a_c;
                ldsm_x4(af[i][0], af[i][1], af[i][2], af[i][3],
                        sA + (uint32_t)(r * SROW + c) * 2);
            }
            #pragma unroll
            for (int jp = 0; jp < 2; jp++) {
                int n = warpn * 32 + jp * 16 + b_r;
                int c = ks * 16 + b_c;
                ldsm_x4(bf[2 * jp][0], bf[2 * jp][1], bf[2 * jp + 1][0], bf[2 * jp + 1][1],
                        sB + (uint32_t)(n * SROW + c) * 2);
            }
            #pragma unroll
            for (int i = 0; i < MI; i++)
                #pragma unroll
                for (int j = 0; j < 4; j++)
                    mma16816(acc[i][j], af[i], bf[j]);
        }
        __syncthreads();
    }

    // ---- epilogue
    const float* pe_row = e.pe ? (e.pe + (size_t)(bm >> 9) * N) : (const float*)0;
    float* Cf = (float*)Cv;
    __half* Ch = (__half*)Cv;

    #pragma unroll
    for (int i = 0; i < MI; i++) {
        const int r0 = bm + warpm * (MI * 16) + i * 16 + fr;
        #pragma unroll
        for (int j = 0; j < 4; j++) {
            const int c0 = bn + warpn * 32 + j * 8 + 2 * fc;
            float v[4];
            #pragma unroll
            for (int k = 0; k < 4; k++) {
                float x = acc[i][j][k];
                const int c = c0 + (k & 1);
                if (e.bias)  x += e.bias[c];
                if (e.bias2) x += e.bias2[c];
                if (pe_row)  x += pe_row[c];
                if (e.act)   x = eluf(x);
                if (e.bn_g)  x = (x - e.bn_m[c]) * e.bn_g[c] * rsqrtf(e.bn_v[c] + EPSF) + e.bn_b[c];
                v[k] = x;
            }
            if (HOUT) {
                *(__half2*)(Ch + (size_t)r0 * ldc + c0)       = __floats2half2_rn(v[0], v[1]);
                *(__half2*)(Ch + (size_t)(r0 + 8) * ldc + c0) = __floats2half2_rn(v[2], v[3]);
            } else {
                *(float2*)(Cf + (size_t)r0 * ldc + c0)        = make_float2(v[0], v[1]);
                *(float2*)(Cf + (size_t)(r0 + 8) * ldc + c0)  = make_float2(v[2], v[3]);
            }
        }
    }
}

// ---------------- preconversion kernels --------------------------------------
__global__ void h_copy4(const float4* __restrict__ src, __half2* __restrict__ dst, int n4)
{
    int i = blockIdx.x * blockDim.x + threadIdx.x;
    if (i < n4) {
        float4 v = src[i];
        dst[2 * i]     = __floats2half2_rn(v.x, v.y);
        dst[2 * i + 1] = __floats2half2_rn(v.z, v.w);
    }
}

__global__ void build_wkv(const float* __restrict__ Wk, const float* __restrict__ Wv)
{
    int idx = blockIdx.x * blockDim.x + threadIdx.x;       // NKV * 256 float4 groups
    int n = idx >> 8, c = (idx & 255) * 4;
    const float* src = (n < Hdim) ? (Wk + (size_t)n * (Hdim + Pdim) + c)
                                  : (Wv + (size_t)(n - Hdim) * (Hdim + Pdim) + c);
    float4 v = *(const float4*)src;
    __half2* d = (__half2*)(g_Wkvh + (size_t)n * Hdim + c);
    d[0] = __floats2half2_rn(v.x, v.y);
    d[1] = __floats2half2_rn(v.z, v.w);
}

__global__ void build_wpre(const float* __restrict__ Wih, const float* __restrict__ Whh,
                           const float* __restrict__ Wac)
{
    int idx = blockIdx.x * blockDim.x + threadIdx.x;       // H4 * 640 float4 groups
    int row = idx / 640, c = (idx - row * 640) * 4;
    const float* src;
    if (c < 512)       src = Wih + (size_t)row * 512 + c;
    else if (c < 1536) src = Whh + (size_t)row * 1024 + (c - 512);
    else               src = Wac + (size_t)row * 1024 + (c - 1536);
    float4 v = *(const float4*)src;
    __half2* d = (__half2*)(g_Wpreh + (size_t)row * KPRE + c);
    d[0] = __floats2half2_rn(v.x, v.y);
    d[1] = __floats2half2_rn(v.z, v.w);
}

__global__ void concat_xh2(const float* __restrict__ x, const float* __restrict__ ph)
{
    int idx = blockIdx.x * blockDim.x + threadIdx.x;       // Bsz * 384 float4 groups
    int row = idx / 384, c = (idx - row * 384) * 4;
    float4 v = (c < 512) ? *(const float4*)(x + (size_t)row * 512 + c)
                         : *(const float4*)(ph + (size_t)row * 1024 + (c - 512));
    __half2* d = (__half2*)(g_xh2h + (size_t)row * KPRE + c);
    d[0] = __floats2half2_rn(v.x, v.y);
    d[1] = __floats2half2_rn(v.z, v.w);
}

__global__ void pe_proj_kernel(const float* __restrict__ Wk, const float* __restrict__ bk,
                               const float* __restrict__ Wv, const float* __restrict__ bv)
{
    int w = blockIdx.x;
    int h = blockIdx.y * blockDim.x + threadIdx.x;
    const float* wkr = Wk + (size_t)h * (Hdim + Pdim) + Hdim;
    const float* wvr = Wv + (size_t)h * (Hdim + Pdim) + Hdim;
    float ak = bk[h], av = bv[h];
    const float c0 = logf(10000.0f) / (float)Pdim;
    #pragma unroll
    for (int i = 0; i < Pdim / 2; i++) {
        float div = expf(-(2.0f * i) * c0);
        float ang = (float)w * div;
        float s = sinf(ang), cc = cosf(ang);
        ak += s * wkr[2 * i] + cc * wkr[2 * i + 1];
        av += s * wvr[2 * i] + cc * wvr[2 * i + 1];
    }
    g_pekv[w * NKV + h]        = ak;
    g_pekv[w * NKV + Hdim + h] = av;
}

// ---------------- attention ---------------------------------------------------
__global__ __launch_bounds__(1024)
void attention_kernel()
{
    int b   = blockIdx.x;
    int tid = threadIdx.x;
    int warp = tid >> 5, lane = tid & 31;

    __shared__ float qs[Hdim];
    __shared__ float S [HEADS][Wwin];
    __shared__ float ps[HEADS][Wwin];

    qs[tid] = g_Q[(size_t)b * Hdim + tid];
    __syncthreads();

    {
        const __half* Krow = g_KV + ((size_t)warp * Bsz + b) * NKV;
        float acc[HEADS];
        #pragma unroll
        for (int h = 0; h < HEADS; h++) acc[h] = 0.f;
        #pragma unroll
        for (int j = 0; j < 32; j++) {
            int d = lane + 32 * j;
            acc[j >> 1] = fmaf(__half2float(Krow[d]), qs[d], acc[j >> 1]);
        }
        #pragma unroll
        for (int h = 0; h < HEADS; h++) {
            float v = acc[h];
            #pragma unroll
            for (int off = 16; off; off >>= 1)
                v += __shfl_down_sync(0xffffffffu, v, off);
            if (lane == 0) S[h][warp] = v * 0.125f;
        }
    }
    __syncthreads();

    if (warp < HEADS) {
        float s = S[warp][lane];
        float m = s;
        #pragma unroll
        for (int off = 16; off; off >>= 1)
            m = fmaxf(m, __shfl_xor_sync(0xffffffffu, m, off));
        float ev = expf(s - m);
        float sum = ev;
        #pragma unroll
        for (int off = 16; off; off >>= 1)
            sum += __shfl_xor_sync(0xffffffffu, sum, off);
        ps[warp][lane] = ev / sum;
    }
    __syncthreads();

    int h = tid >> 6;
    const __half* Vb = g_KV + (size_t)b * NKV + Hdim + tid;
    float acc = 0.f;
    #pragma unroll
    for (int w = 0; w < Wwin; w++)
        acc = fmaf(ps[h][w], __half2float(Vb[(size_t)w * Bsz * NKV]), acc);
    g_ctxh[(size_t)b * Hdim + tid] = __float2half_rn(acc);
}

__global__ void final_kernel(const float* __restrict__ pcell,
                             const float* __restrict__ gmm, const float* __restrict__ bb,
                             const float* __restrict__ mm, const float* __restrict__ vv,
                             float* __restrict__ out)
{
    int idx = blockIdx.x * blockDim.x + threadIdx.x;
    int r = idx >> 10, c = idx & 1023;
    const float* p = g_pre + (size_t)r * H4;
    float iv = tanhf(p[c]);
    float f  = 1.f / (1.f + expf(-p[1024 + c]));
    float ig = 1.f / (1.f + expf(-p[2048 + c]));
    float o  = 1.f / (1.f + expf(-p[3072 + c]));
    float cell = iv * ig + pcell[idx] * f;
    float e = eluf(cell);
    out[idx] = (o * e - mm[c]) * gmm[c] * rsqrtf(vv[c] + EPSF) + bb[c];
}

// ---------------- host --------------------------------------------------------
#define SMEM_MI2 ((64 + 128) * SROW * 3 * 2)
#define SMEM_MI4 ((128 + 128) * SROW * 3 * 2)

static void h_arr(const float* src, __half* dst, size_t n)
{
    int n4 = (int)(n / 4);
    h_copy4<<<(n4 + 255) / 256, 256>>>((const float4*)src, (__half2*)dst, n4);
}

extern "C" void kernel_launch(void* const* d_in, const int* in_sizes, int n_in,
                              void* d_out, int out_size)
{
    const float* x      = (const float*)d_in[0];
    const float* ph     = (const float*)d_in[1];
    const float* pc     = (const float*)d_in[2];
    const float* pcells = (const float*)d_in[3];
    const float* W_ih   = (const float*)d_in[4];
    const float* b_ih   = (const float*)d_in[5];
    const float* W_hh   = (const float*)d_in[6];
    const float* W_q    = (const float*)d_in[7];
    const float* b_q    = (const float*)d_in[8];
    const float* W_ac   = (const float*)d_in[9];
    const float* b_ac   = (const float*)d_in[10];
    const float* Wq_a   = (const float*)d_in[11];
    const float* bq_a   = (const float*)d_in[12];
    const float* Wk_a   = (const float*)d_in[13];
    const float* bk_a   = (const float*)d_in[14];
    const float* Wv_a   = (const float*)d_in[15];
    const float* bv_a   = (const float*)d_in[16];
    const float* Wo_a   = (const float*)d_in[17];
    const float* bo_a   = (const float*)d_in[18];
    const float* bnag   = (const float*)d_in[19];
    const float* bnab   = (const float*)d_in[20];
    const float* bnam   = (const float*)d_in[21];
    const float* bnav   = (const float*)d_in[22];
    const float* bnpg   = (const float*)d_in[23];
    const float* bnpb   = (const float*)d_in[24];
    const float* bnpm   = (const float*)d_in[25];
    const float* bnpv   = (const float*)d_in[26];
    float* out = (float*)d_out;

    cudaFuncSetAttribute(hgemm<2,0>, cudaFuncAttributeMaxDynamicSharedMemorySize, SMEM_MI2);
    cudaFuncSetAttribute(hgemm<2,1>, cudaFuncAttributeMaxDynamicSharedMemorySize, SMEM_MI2);
    cudaFuncSetAttribute(hgemm<4,1>, cudaFuncAttributeMaxDynamicSharedMemorySize, SMEM_MI4);

    __half *pxh2, *pqh, *pKV, *pctxh, *ppch, *pWqh, *pWqah, *pWkvh, *pWoh, *pWpreh;
    float *pQ, *ppekv, *ppre;
    cudaGetSymbolAddress((void**)&pxh2,  g_xh2h);
    cudaGetSymbolAddress((void**)&pqh,   g_qh);
    cudaGetSymbolAddress((void**)&pQ,    g_Q);
    cudaGetSymbolAddress((void**)&ppekv, g_pekv);
    cudaGetSymbolAddress((void**)&pKV,   g_KV);
    cudaGetSymbolAddress((void**)&pctxh, g_ctxh);
    cudaGetSymbolAddress((void**)&ppre,  g_pre);
    cudaGetSymbolAddress((void**)&ppch,  g_pch);
    cudaGetSymbolAddress((void**)&pWqh,  g_Wqh);
    cudaGetSymbolAddress((void**)&pWqah, g_Wqah);
    cudaGetSymbolAddress((void**)&pWkvh, g_Wkvh);
    cudaGetSymbolAddress((void**)&pWoh,  g_Woh);
    cudaGetSymbolAddress((void**)&pWpreh,g_Wpreh);

    // ---- preconversion to fp16
    concat_xh2<<<(Bsz * 384 + 255) / 256, 256>>>(x, ph);
    pe_proj_kernel<<<dim3(Wwin, Hdim / 128), 128>>>(Wk_a, bk_a, Wv_a, bv_a);
    h_arr(pcells, ppch, (size_t)Wwin * Bsz * Hdim);
    h_arr(W_q,  pWqh,  (size_t)Hdim * KQ);
    h_arr(Wq_a, pWqah, (size_t)Hdim * Hdim);
    h_arr(Wo_a, pWoh,  (size_t)Hdim * Hdim);
    build_wkv<<<(NKV * 256 + 255) / 256, 256>>>(Wk_a, Wv_a);
    build_wpre<<<(H4 * 640 + 255) / 256, 256>>>(W_ih, W_hh, W_ac);

    Epi e0 = {};

    // q = elu(xh @ W_q^T + b_q)  -> fp16
    { Epi e = e0; e.bias = b_q; e.act = 1;
      hgemm<2,1><<<dim3(Hdim/128, Bsz/64), 256, SMEM_MI2>>>(
          pxh2, pWqh, pqh, Bsz, Hdim, KQ, KPRE, KQ, Hdim, e); }

    // Q = q @ Wq_a^T + bq_a  -> f32
    { Epi e = e0; e.bias = bq_a;
      hgemm<2,0><<<dim3(Hdim/128, Bsz/64), 256, SMEM_MI2>>>(
          pqh, pWqah, pQ, Bsz, Hdim, Hdim, Hdim, Hdim, Hdim, e); }

    // [K|V] = elu(pcells @ [Wk;Wv]^T + pe[w])  -> fp16, layout [W,B,2048]
    { Epi e = e0; e.pe = ppekv; e.act = 1;
      hgemm<4,1><<<dim3(NKV/128, (Wwin*Bsz)/128), 256, SMEM_MI4>>>(
          ppch, pWkvh, pKV, Wwin*Bsz, NKV, Hdim, Hdim, Hdim, NKV, e); }

    // attention -> ctx (fp16)
    attention_kernel<<<Bsz, 1024>>>();

    // attn = BN(elu(ctx @ Wo_a^T + bo_a)) -> fp16, into xh2 cols [1536,2560)
    { Epi e = e0; e.bias = bo_a; e.act = 1;
      e.bn_g = bnag; e.bn_b = bnab; e.bn_m = bnam; e.bn_v = bnav;
      hgemm<2,1><<<dim3(Hdim/128, Bsz/64), 256, SMEM_MI2>>>(
          pctxh, pWoh, pxh2 + KQ, Bsz, Hdim, Hdim, Hdim, Hdim, KPRE, e); }

    // pre = [x|ph|attn] @ [W_ih|W_hh|W_ac]^T + b_ih + b_ac  -> f32
    { Epi e = e0; e.bias = b_ih; e.bias2 = b_ac;
      hgemm<2,0><<<dim3(H4/128, Bsz/64), 256, SMEM_MI2>>>(
          pxh2, pWpreh, ppre, Bsz, H4, KPRE, KPRE, KPRE, H4, e); }

    // LSTM tail + post-BN -> out
    final_kernel<<<(Bsz * Hdim) / 256, 256>>>(pc, bnpg, bnpb, bnpm, bnpv, out);
}